// round 9
// baseline (speedup 1.0000x reference)
#include <cuda_runtime.h>

#define NN 100000
#define F1 128
#define F2 64
#define F3 40
#define EMAX 1700000
#define NB 391  // ceil(NN/256)

// ---------------- scratch ---------------------------------------------------
__device__ int   g_deg[NN];
__device__ float g_dis[NN];
__device__ int   g_off[NN + 1];
__device__ int   g_cur[NN];
__device__ int   g_bsum[512];
__device__ int   g_csr[EMAX];
__device__ __align__(16) float g_xws[NN * F2];  // (x@W1)*dis, natural [r][64]
__device__ __align__(16) float g_h[NN * F2];    // relu out, natural [r][64]
__device__ __align__(16) float g_hwf[NN * F3];  // (h@W2)*dis, natural [r][40]
__device__ int g_is64;

// ---------------- tf32 helpers ----------------------------------------------
__device__ __forceinline__ unsigned f2tf32(float f) {
    unsigned r;
    asm("cvt.rna.tf32.f32 %0, %1;" : "=r"(r) : "f"(f));
    return r;
}
__device__ __forceinline__ void mma1688(float* c, const unsigned* a, const unsigned* b) {
    asm volatile(
        "mma.sync.aligned.m16n8k8.row.col.f32.tf32.tf32.f32 "
        "{%0,%1,%2,%3}, {%4,%5,%6,%7}, {%8,%9}, {%0,%1,%2,%3};"
        : "+f"(c[0]), "+f"(c[1]), "+f"(c[2]), "+f"(c[3])
        : "r"(a[0]), "r"(a[1]), "r"(a[2]), "r"(a[3]), "r"(b[0]), "r"(b[1]));
}

// ---------------- edge index fetch (dtype-agnostic) -------------------------
__device__ __forceinline__ int edge_idx(const void* ei, long long E,
                                        long long e, int which) {
    if (g_is64) return (int)((const long long*)ei)[(long long)which * E + e];
    return ((const int*)ei)[(long long)which * E + e];
}

// ---------------- init: dtype probe + zero degree ---------------------------
__global__ void k_init(const int* __restrict__ ei) {
    int i = blockIdx.x * blockDim.x + threadIdx.x;
    if (i < NN) g_deg[i] = 0;
    if (i == 0) {
        int ones = 0;
        for (int j = 0; j < 256; j++) ones |= ei[2 * j + 1];
        g_is64 = (ones == 0) ? 1 : 0;
    }
}

__global__ void k_deg(const void* __restrict__ ei, int E) {
    int i = blockIdx.x * blockDim.x + threadIdx.x;
    if (i >= E) return;
    int d = edge_idx(ei, E, i, 1);
    if ((unsigned)d < NN) atomicAdd(&g_deg[d], 1);
}

// ---------------- dis + scan step 1 -----------------------------------------
__global__ void k_dis_scan1() {
    __shared__ int wsum[8];
    int i = blockIdx.x * 256 + threadIdx.x;
    int lane = threadIdx.x & 31, w = threadIdx.x >> 5;
    int deg = (i < NN) ? g_deg[i] : 0;
    if (i < NN) g_dis[i] = rsqrtf((float)(deg + 1));
    int incl = deg;
    #pragma unroll
    for (int o = 1; o < 32; o <<= 1) {
        int t = __shfl_up_sync(0xffffffffu, incl, o);
        if (lane >= o) incl += t;
    }
    if (lane == 31) wsum[w] = incl;
    __syncthreads();
    if (w == 0) {
        int s = (lane < 8) ? wsum[lane] : 0;
        #pragma unroll
        for (int o = 1; o < 8; o <<= 1) {
            int t = __shfl_up_sync(0xffffffffu, s, o);
            if (lane >= o) s += t;
        }
        if (lane < 8) wsum[lane] = s;
    }
    __syncthreads();
    if (w > 0) incl += wsum[w - 1];
    if (i < NN) g_off[i + 1] = incl;
    if (threadIdx.x == 255) g_bsum[blockIdx.x] = incl;
}

__global__ void k_scan2() {
    __shared__ int s[512];
    int t = threadIdx.x;
    s[t] = (t < NB) ? g_bsum[t] : 0;
    __syncthreads();
    for (int o = 1; o < 512; o <<= 1) {
        int v = (t >= o) ? s[t - o] : 0;
        __syncthreads();
        s[t] += v;
        __syncthreads();
    }
    if (t < NB) g_bsum[t] = (t > 0) ? s[t - 1] : 0;
}

__global__ void k_scan3() {
    int j = blockIdx.x * blockDim.x + threadIdx.x;
    if (j > NN) return;
    int v = (j == 0) ? 0 : g_off[j] + g_bsum[(j - 1) >> 8];
    g_off[j] = v;
    if (j < NN) g_cur[j] = v;
}

__global__ void k_fill(const void* __restrict__ ei, int E) {
    int e = blockIdx.x * blockDim.x + threadIdx.x;
    if (e >= E) return;
    int s = edge_idx(ei, E, e, 0);
    int d = edge_idx(ei, E, e, 1);
    if ((unsigned)s >= NN || (unsigned)d >= NN) return;
    int pos = atomicAdd(&g_cur[d], 1);
    if (pos < EMAX) g_csr[pos] = s;
}

// ---------------- GEMM1 (tf32 tensor, 3xTF32): 128x64/block -----------------
// 8 warps; warp (w&3, w>>2) computes rows [m0,m0+32) x cols [n0,n0+32).
__global__ void k_gemm1(const float* __restrict__ X, const float* __restrict__ W) {
    __shared__ unsigned XsH[128][20], XsL[128][20];  // [row][k] (+4 pad)
    __shared__ unsigned WsH[16][72], WsL[16][72];    // [k][col]
    int tid = threadIdx.x;
    int lane = tid & 31, w = tid >> 5;
    int rbase = blockIdx.x * 128;
    int m0 = (w & 3) * 32;
    int n0 = (w >> 2) * 32;
    int ra = lane >> 2, qa = lane & 3;

    float c[2][4][4];
    #pragma unroll
    for (int mt = 0; mt < 2; mt++)
        #pragma unroll
        for (int nt = 0; nt < 4; nt++)
            #pragma unroll
            for (int j = 0; j < 4; j++) c[mt][nt][j] = 0.f;

    #pragma unroll 1
    for (int kc = 0; kc < F1; kc += 16) {
        #pragma unroll
        for (int it = 0; it < 2; it++) {
            int lin = tid + it * 256;      // 0..511 -> (row, q)
            int row = lin >> 2, q = lin & 3;
            int rr = min(rbase + row, NN - 1);
            float4 v = *(const float4*)(X + (size_t)rr * F1 + kc + q * 4);
            float vv[4] = {v.x, v.y, v.z, v.w};
            #pragma unroll
            for (int j = 0; j < 4; j++) {
                unsigned hi = f2tf32(vv[j]);
                XsH[row][q * 4 + j] = hi;
                XsL[row][q * 4 + j] = f2tf32(vv[j] - __uint_as_float(hi));
            }
        }
        {
            int k = tid >> 4, c4 = tid & 15;
            float4 v = *(const float4*)(W + (size_t)(kc + k) * F2 + c4 * 4);
            float vv[4] = {v.x, v.y, v.z, v.w};
            #pragma unroll
            for (int j = 0; j < 4; j++) {
                unsigned hi = f2tf32(vv[j]);
                WsH[k][c4 * 4 + j] = hi;
                WsL[k][c4 * 4 + j] = f2tf32(vv[j] - __uint_as_float(hi));
            }
        }
        __syncthreads();
        #pragma unroll
        for (int ks = 0; ks < 2; ks++) {
            int ka = ks * 8 + qa;
            unsigned aH[2][4], aL[2][4];
            #pragma unroll
            for (int mt = 0; mt < 2; mt++) {
                int r0 = m0 + mt * 16 + ra;
                aH[mt][0] = XsH[r0][ka];     aH[mt][1] = XsH[r0 + 8][ka];
                aH[mt][2] = XsH[r0][ka + 4]; aH[mt][3] = XsH[r0 + 8][ka + 4];
                aL[mt][0] = XsL[r0][ka];     aL[mt][1] = XsL[r0 + 8][ka];
                aL[mt][2] = XsL[r0][ka + 4]; aL[mt][3] = XsL[r0 + 8][ka + 4];
            }
            unsigned bH[4][2], bL[4][2];
            #pragma unroll
            for (int nt = 0; nt < 4; nt++) {
                int cb = n0 + nt * 8 + ra;
                bH[nt][0] = WsH[ka][cb]; bH[nt][1] = WsH[ka + 4][cb];
                bL[nt][0] = WsL[ka][cb]; bL[nt][1] = WsL[ka + 4][cb];
            }
            #pragma unroll
            for (int mt = 0; mt < 2; mt++)
                #pragma unroll
                for (int nt = 0; nt < 4; nt++) {
                    mma1688(c[mt][nt], aH[mt], bH[nt]);
                    mma1688(c[mt][nt], aH[mt], bL[nt]);
                    mma1688(c[mt][nt], aL[mt], bH[nt]);
                }
        }
        __syncthreads();
    }

    #pragma unroll
    for (int mt = 0; mt < 2; mt++) {
        int r0 = rbase + m0 + mt * 16 + ra;
        int r1 = r0 + 8;
        float d0 = (r0 < NN) ? g_dis[r0] : 0.f;
        float d1 = (r1 < NN) ? g_dis[r1] : 0.f;
        #pragma unroll
        for (int nt = 0; nt < 4; nt++) {
            int col = n0 + nt * 8 + 2 * qa;
            if (r0 < NN)
                *(float2*)(g_xws + (size_t)r0 * F2 + col) =
                    make_float2(c[mt][nt][0] * d0, c[mt][nt][1] * d0);
            if (r1 < NN)
                *(float2*)(g_xws + (size_t)r1 * F2 + col) =
                    make_float2(c[mt][nt][2] * d1, c[mt][nt][3] * d1);
        }
    }
}

// ---------------- agg1: float4 gather, 2 edges/warp in flight ---------------
__global__ void k_agg1(const float* __restrict__ b1) {
    int lane = threadIdx.x & 31;
    int c4 = lane & 15;
    int half = lane >> 4;
    int n = blockIdx.x * 8 + (threadIdx.x >> 5);
    if (n >= NN) return;
    int beg = g_off[n], end = g_off[n + 1];
    const float4* xws4 = (const float4*)g_xws;

    float4 acc = make_float4(0.f, 0.f, 0.f, 0.f);
    if (half == 1) acc = xws4[(size_t)n * 16 + c4];

    for (int base = beg; base < end; base += 32) {
        int cnt = min(32, end - base);
        int sl = (lane < cnt) ? g_csr[base + lane] : 0;
        int k = 0;
        for (; k + 1 < cnt; k += 2) {
            int s = __shfl_sync(0xffffffffu, sl, k + half);
            float4 v = xws4[(size_t)s * 16 + c4];
            acc.x += v.x; acc.y += v.y; acc.z += v.z; acc.w += v.w;
        }
        if (k < cnt) {
            int s = __shfl_sync(0xffffffffu, sl, k);
            if (half == 0) {
                float4 v = xws4[(size_t)s * 16 + c4];
                acc.x += v.x; acc.y += v.y; acc.z += v.z; acc.w += v.w;
            }
        }
    }
    acc.x += __shfl_xor_sync(0xffffffffu, acc.x, 16);
    acc.y += __shfl_xor_sync(0xffffffffu, acc.y, 16);
    acc.z += __shfl_xor_sync(0xffffffffu, acc.z, 16);
    acc.w += __shfl_xor_sync(0xffffffffu, acc.w, 16);

    if (half == 0) {
        float d = g_dis[n];
        float4 bb = *(const float4*)(b1 + c4 * 4);
        float4 o = make_float4(fmaxf(d * acc.x + bb.x, 0.f),
                               fmaxf(d * acc.y + bb.y, 0.f),
                               fmaxf(d * acc.z + bb.z, 0.f),
                               fmaxf(d * acc.w + bb.w, 0.f));
        *(float4*)(g_h + (size_t)n * F2 + c4 * 4) = o;
    }
}

// ---------------- GEMM2 (tf32 tensor): 128x40/block, 8 warps ----------------
// warp w computes rows [w*16, w*16+16) x all 40 cols (5 n-tiles).
__global__ void k_gemm2(const float* __restrict__ W) {
    __shared__ unsigned XsH[128][20], XsL[128][20];  // [row][k]
    __shared__ unsigned WsH[64][40], WsL[64][40];    // [k][col]
    int tid = threadIdx.x;
    int lane = tid & 31, w = tid >> 5;
    int rbase = blockIdx.x * 128;
    int m0 = w * 16;
    int ra = lane >> 2, qa = lane & 3;

    // stage full W2 hi/lo once
    for (int idx = tid; idx < F2 * F3; idx += 256) {
        int k = idx / F3, n = idx % F3;
        float v = W[idx];
        unsigned hi = f2tf32(v);
        WsH[k][n] = hi;
        WsL[k][n] = f2tf32(v - __uint_as_float(hi));
    }
    __syncthreads();

    float c[5][4];
    #pragma unroll
    for (int nt = 0; nt < 5; nt++)
        #pragma unroll
        for (int j = 0; j < 4; j++) c[nt][j] = 0.f;

    #pragma unroll 1
    for (int kc = 0; kc < F2; kc += 16) {
        #pragma unroll
        for (int it = 0; it < 2; it++) {
            int lin = tid + it * 256;
            int row = lin >> 2, q = lin & 3;
            int rr = min(rbase + row, NN - 1);
            float4 v = *(const float4*)(g_h + (size_t)rr * F2 + kc + q * 4);
            float vv[4] = {v.x, v.y, v.z, v.w};
            #pragma unroll
            for (int j = 0; j < 4; j++) {
                unsigned hi = f2tf32(vv[j]);
                XsH[row][q * 4 + j] = hi;
                XsL[row][q * 4 + j] = f2tf32(vv[j] - __uint_as_float(hi));
            }
        }
        __syncthreads();
        #pragma unroll
        for (int ks = 0; ks < 2; ks++) {
            int ka = ks * 8 + qa;
            int kb = kc + ka;
            unsigned aH[4], aL[4];
            int r0 = m0 + ra;
            aH[0] = XsH[r0][ka];     aH[1] = XsH[r0 + 8][ka];
            aH[2] = XsH[r0][ka + 4]; aH[3] = XsH[r0 + 8][ka + 4];
            aL[0] = XsL[r0][ka];     aL[1] = XsL[r0 + 8][ka];
            aL[2] = XsL[r0][ka + 4]; aL[3] = XsL[r0 + 8][ka + 4];
            #pragma unroll
            for (int nt = 0; nt < 5; nt++) {
                int cb = nt * 8 + ra;
                unsigned bH[2], bL[2];
                bH[0] = WsH[kb][cb]; bH[1] = WsH[kb + 4][cb];
                bL[0] = WsL[kb][cb]; bL[1] = WsL[kb + 4][cb];
                mma1688(c[nt], aH, bH);
                mma1688(c[nt], aH, bL);
                mma1688(c[nt], aL, bH);
            }
        }
        __syncthreads();
    }

    int r0 = rbase + m0 + ra;
    int r1 = r0 + 8;
    float d0 = (r0 < NN) ? g_dis[r0] : 0.f;
    float d1 = (r1 < NN) ? g_dis[r1] : 0.f;
    #pragma unroll
    for (int nt = 0; nt < 5; nt++) {
        int col = nt * 8 + 2 * qa;
        if (r0 < NN)
            *(float2*)(g_hwf + (size_t)r0 * F3 + col) =
                make_float2(c[nt][0] * d0, c[nt][1] * d0);
        if (r1 < NN)
            *(float2*)(g_hwf + (size_t)r1 * F3 + col) =
                make_float2(c[nt][2] * d1, c[nt][3] * d1);
    }
}

// ---------------- agg2: reduce + self + bias + log-softmax ------------------
__global__ void k_agg2(const float* __restrict__ b2, float* __restrict__ out) {
    int lane = threadIdx.x & 31;
    int n = blockIdx.x * 8 + (threadIdx.x >> 5);
    if (n >= NN) return;
    bool act = lane < 20;
    const float2* hw2 = (const float2*)g_hwf;
    int beg = g_off[n], end = g_off[n + 1];

    float2 accA = act ? hw2[(size_t)n * 20 + lane] : make_float2(0.f, 0.f);
    float2 accB = make_float2(0.f, 0.f);

    for (int base = beg; base < end; base += 32) {
        int cnt = min(32, end - base);
        int sl = (lane < cnt) ? g_csr[base + lane] : 0;
        int k = 0;
        for (; k + 1 < cnt; k += 2) {
            int s0 = __shfl_sync(0xffffffffu, sl, k);
            int s1 = __shfl_sync(0xffffffffu, sl, k + 1);
            if (act) {
                float2 v0 = hw2[(size_t)s0 * 20 + lane];
                float2 v1 = hw2[(size_t)s1 * 20 + lane];
                accA.x += v0.x; accA.y += v0.y;
                accB.x += v1.x; accB.y += v1.y;
            }
        }
        if (k < cnt) {
            int s0 = __shfl_sync(0xffffffffu, sl, k);
            if (act) {
                float2 v = hw2[(size_t)s0 * 20 + lane];
                accA.x += v.x; accA.y += v.y;
            }
        }
    }

    float d = g_dis[n];
    float zx = act ? d * (accA.x + accB.x) + b2[2 * lane]     : -3.4e38f;
    float zy = act ? d * (accA.y + accB.y) + b2[2 * lane + 1] : -3.4e38f;

    float m = fmaxf(zx, zy);
    #pragma unroll
    for (int o = 16; o; o >>= 1) m = fmaxf(m, __shfl_xor_sync(0xffffffffu, m, o));
    float s = act ? (expf(zx - m) + expf(zy - m)) : 0.f;
    #pragma unroll
    for (int o = 16; o; o >>= 1) s += __shfl_xor_sync(0xffffffffu, s, o);
    float lse = m + logf(s);

    if (act) {
        out[(size_t)n * F3 + 2 * lane]     = zx - lse;
        out[(size_t)n * F3 + 2 * lane + 1] = zy - lse;
    }
}

// ---------------- launcher --------------------------------------------------
extern "C" void kernel_launch(void* const* d_in, const int* in_sizes, int n_in,
                              void* d_out, int out_size) {
    const float* x  = (const float*)d_in[0];
    const void*  ei = d_in[1];
    const float* W1 = (const float*)d_in[2];
    const float* b1 = (const float*)d_in[3];
    const float* W2 = (const float*)d_in[4];
    const float* b2 = (const float*)d_in[5];
    float* out = (float*)d_out;

    int E = in_sizes[1] / 2;
    int eb = (E + 255) / 256;

    static cudaStream_t s2 = 0;
    static cudaEvent_t evA = 0, evB = 0;
    if (!s2) {
        cudaStreamCreateWithFlags(&s2, cudaStreamNonBlocking);
        cudaEventCreateWithFlags(&evA, cudaEventDisableTiming);
        cudaEventCreateWithFlags(&evB, cudaEventDisableTiming);
    }

    k_init<<<NB, 256>>>((const int*)ei);
    k_deg<<<eb, 256>>>(ei, E);
    k_dis_scan1<<<NB, 256>>>();

    // fork: gemm1 (needs only x, W1, dis) overlaps the CSR build
    cudaEventRecord(evA, 0);
    cudaStreamWaitEvent(s2, evA, 0);
    k_gemm1<<<(NN + 127) / 128, 256, 0, s2>>>(x, W1);
    cudaEventRecord(evB, s2);

    k_scan2<<<1, 512>>>();
    k_scan3<<<(NN + 256) / 256, 256>>>();
    k_fill<<<eb, 256>>>(ei, E);

    cudaStreamWaitEvent(0, evB, 0);  // join before agg1

    k_agg1<<<(NN + 7) / 8, 256>>>(b1);
    k_gemm2<<<(NN + 127) / 128, 256>>>(W2);
    k_agg2<<<(NN + 7) / 8, 256>>>(b2, out);
}

// round 10
// speedup vs baseline: 1.0916x; 1.0916x over previous
#include <cuda_runtime.h>

#define NN 100000
#define F1 128
#define F2 64
#define F3 40
#define EMAX 1700000
#define NB 391  // ceil(NN/256)

// ---------------- scratch ---------------------------------------------------
__device__ int   g_deg[NN];
__device__ float g_dis[NN];
__device__ int   g_off[NN + 1];
__device__ int   g_cur[NN];
__device__ int   g_bsum[512];
__device__ int   g_csr[EMAX];
__device__ __align__(16) float g_xws[NN * F2];  // (x@W1)*dis, natural [r][64]
__device__ __align__(16) float g_h[NN * F2];    // relu out, natural [r][64]
__device__ __align__(16) float g_hwf[NN * F3];  // (h@W2)*dis, natural [r][40]
__device__ int g_is64;

// ---------------- edge index fetch (dtype-agnostic) -------------------------
__device__ __forceinline__ int edge_idx(const void* ei, long long E,
                                        long long e, int which) {
    if (g_is64) return (int)((const long long*)ei)[(long long)which * E + e];
    return ((const int*)ei)[(long long)which * E + e];
}

// ---------------- init: dtype probe + zero degree ---------------------------
__global__ void k_init(const int* __restrict__ ei) {
    int i = blockIdx.x * blockDim.x + threadIdx.x;
    if (i < NN) g_deg[i] = 0;
    if (i == 0) {
        int ones = 0;
        for (int j = 0; j < 256; j++) ones |= ei[2 * j + 1];
        g_is64 = (ones == 0) ? 1 : 0;
    }
}

__global__ void k_deg(const void* __restrict__ ei, int E) {
    int i = blockIdx.x * blockDim.x + threadIdx.x;
    if (i >= E) return;
    int d = edge_idx(ei, E, i, 1);
    if ((unsigned)d < NN) atomicAdd(&g_deg[d], 1);
}

// ---------------- dis + scan step 1 -----------------------------------------
__global__ void k_dis_scan1() {
    __shared__ int wsum[8];
    int i = blockIdx.x * 256 + threadIdx.x;
    int lane = threadIdx.x & 31, w = threadIdx.x >> 5;
    int deg = (i < NN) ? g_deg[i] : 0;
    if (i < NN) g_dis[i] = rsqrtf((float)(deg + 1));
    int incl = deg;
    #pragma unroll
    for (int o = 1; o < 32; o <<= 1) {
        int t = __shfl_up_sync(0xffffffffu, incl, o);
        if (lane >= o) incl += t;
    }
    if (lane == 31) wsum[w] = incl;
    __syncthreads();
    if (w == 0) {
        int s = (lane < 8) ? wsum[lane] : 0;
        #pragma unroll
        for (int o = 1; o < 8; o <<= 1) {
            int t = __shfl_up_sync(0xffffffffu, s, o);
            if (lane >= o) s += t;
        }
        if (lane < 8) wsum[lane] = s;
    }
    __syncthreads();
    if (w > 0) incl += wsum[w - 1];
    if (i < NN) g_off[i + 1] = incl;
    if (threadIdx.x == 255) g_bsum[blockIdx.x] = incl;
}

__global__ void k_scan2() {
    __shared__ int s[512];
    int t = threadIdx.x;
    s[t] = (t < NB) ? g_bsum[t] : 0;
    __syncthreads();
    for (int o = 1; o < 512; o <<= 1) {
        int v = (t >= o) ? s[t - o] : 0;
        __syncthreads();
        s[t] += v;
        __syncthreads();
    }
    if (t < NB) g_bsum[t] = (t > 0) ? s[t - 1] : 0;
}

__global__ void k_scan3() {
    int j = blockIdx.x * blockDim.x + threadIdx.x;
    if (j > NN) return;
    int v = (j == 0) ? 0 : g_off[j] + g_bsum[(j - 1) >> 8];
    g_off[j] = v;
    if (j < NN) g_cur[j] = v;
}

__global__ void k_fill(const void* __restrict__ ei, int E) {
    int e = blockIdx.x * blockDim.x + threadIdx.x;
    if (e >= E) return;
    int s = edge_idx(ei, E, e, 0);
    int d = edge_idx(ei, E, e, 1);
    if ((unsigned)s >= NN || (unsigned)d >= NN) return;
    int pos = atomicAdd(&g_cur[d], 1);
    if (pos < EMAX) g_csr[pos] = s;
}

// ---------------- GEMM1: 128x64 block, 8x4 micro-tile, 256 thr --------------
__global__ void __launch_bounds__(256, 4)
k_gemm1(const float* __restrict__ X, const float* __restrict__ W) {
    __shared__ float Xs[16][128];  // [k][row]
    __shared__ float Ws[16][64];   // [k][col]
    int tid = threadIdx.x;
    int rbase = blockIdx.x * 128;
    int m0 = (tid >> 4) * 8;       // 0..120
    int n0 = (tid & 15) * 4;       // 0..60

    float c[8][4] = {};

    #pragma unroll 1
    for (int kc = 0; kc < F1; kc += 16) {
        #pragma unroll
        for (int it = 0; it < 2; it++) {
            int idx = tid + it * 256;
            int row = idx >> 2, q = idx & 3;
            int rr = min(rbase + row, NN - 1);
            float4 v = *(const float4*)(X + (size_t)rr * F1 + kc + q * 4);
            Xs[q * 4 + 0][row] = v.x;
            Xs[q * 4 + 1][row] = v.y;
            Xs[q * 4 + 2][row] = v.z;
            Xs[q * 4 + 3][row] = v.w;
        }
        {
            int k = tid >> 4, c4 = tid & 15;
            float4 v = *(const float4*)(W + (size_t)(kc + k) * F2 + c4 * 4);
            *(float4*)&Ws[k][c4 * 4] = v;
        }
        __syncthreads();
        #pragma unroll
        for (int k = 0; k < 16; k++) {
            float4 a0 = *(float4*)&Xs[k][m0];
            float4 a1 = *(float4*)&Xs[k][m0 + 4];
            float4 b  = *(float4*)&Ws[k][n0];
            float av[8] = {a0.x, a0.y, a0.z, a0.w, a1.x, a1.y, a1.z, a1.w};
            #pragma unroll
            for (int i = 0; i < 8; i++) {
                c[i][0] = fmaf(av[i], b.x, c[i][0]);
                c[i][1] = fmaf(av[i], b.y, c[i][1]);
                c[i][2] = fmaf(av[i], b.z, c[i][2]);
                c[i][3] = fmaf(av[i], b.w, c[i][3]);
            }
        }
        __syncthreads();
    }

    #pragma unroll
    for (int i = 0; i < 8; i++) {
        int r = rbase + m0 + i;
        if (r < NN) {
            float d = g_dis[r];
            float4 o = make_float4(c[i][0] * d, c[i][1] * d, c[i][2] * d, c[i][3] * d);
            *(float4*)(g_xws + (size_t)r * F2 + n0) = o;
        }
    }
}

// ---------------- agg1: float4 gather, 8 edges / 4 LDG-waves in flight ------
__global__ void k_agg1(const float* __restrict__ b1) {
    int lane = threadIdx.x & 31;
    int c4 = lane & 15;     // float4 chunk
    int half = lane >> 4;   // 0 or 1
    int n = blockIdx.x * 8 + (threadIdx.x >> 5);
    if (n >= NN) return;
    int beg = g_off[n], end = g_off[n + 1];
    const float4* xws4 = (const float4*)g_xws;

    float4 aA = make_float4(0.f, 0.f, 0.f, 0.f);
    float4 aB = make_float4(0.f, 0.f, 0.f, 0.f);
    float4 aC = make_float4(0.f, 0.f, 0.f, 0.f);
    float4 aD = make_float4(0.f, 0.f, 0.f, 0.f);
    if (half == 1) aA = xws4[(size_t)n * 16 + c4];  // self-loop

    for (int base = beg; base < end; base += 32) {
        int cnt = min(32, end - base);
        int sl = (lane < cnt) ? g_csr[base + lane] : 0;
        int k = 0;
        // 4 independent waves = 4 LDG.128 in flight per lane (8 edges/warp)
        for (; k + 7 < cnt; k += 8) {
            int sA = __shfl_sync(0xffffffffu, sl, k + half);
            int sB = __shfl_sync(0xffffffffu, sl, k + 2 + half);
            int sC = __shfl_sync(0xffffffffu, sl, k + 4 + half);
            int sD = __shfl_sync(0xffffffffu, sl, k + 6 + half);
            float4 vA = xws4[(size_t)sA * 16 + c4];
            float4 vB = xws4[(size_t)sB * 16 + c4];
            float4 vC = xws4[(size_t)sC * 16 + c4];
            float4 vD = xws4[(size_t)sD * 16 + c4];
            aA.x += vA.x; aA.y += vA.y; aA.z += vA.z; aA.w += vA.w;
            aB.x += vB.x; aB.y += vB.y; aB.z += vB.z; aB.w += vB.w;
            aC.x += vC.x; aC.y += vC.y; aC.z += vC.z; aC.w += vC.w;
            aD.x += vD.x; aD.y += vD.y; aD.z += vD.z; aD.w += vD.w;
        }
        for (; k + 1 < cnt; k += 2) {
            int s = __shfl_sync(0xffffffffu, sl, k + half);
            float4 v = xws4[(size_t)s * 16 + c4];
            aA.x += v.x; aA.y += v.y; aA.z += v.z; aA.w += v.w;
        }
        if (k < cnt) {
            int s = __shfl_sync(0xffffffffu, sl, k);
            if (half == 0) {
                float4 v = xws4[(size_t)s * 16 + c4];
                aA.x += v.x; aA.y += v.y; aA.z += v.z; aA.w += v.w;
            }
        }
    }
    float4 acc = make_float4(aA.x + aB.x + aC.x + aD.x,
                             aA.y + aB.y + aC.y + aD.y,
                             aA.z + aB.z + aC.z + aD.z,
                             aA.w + aB.w + aC.w + aD.w);
    acc.x += __shfl_xor_sync(0xffffffffu, acc.x, 16);
    acc.y += __shfl_xor_sync(0xffffffffu, acc.y, 16);
    acc.z += __shfl_xor_sync(0xffffffffu, acc.z, 16);
    acc.w += __shfl_xor_sync(0xffffffffu, acc.w, 16);

    if (half == 0) {
        float d = g_dis[n];
        float4 bb = *(const float4*)(b1 + c4 * 4);
        float4 o = make_float4(fmaxf(d * acc.x + bb.x, 0.f),
                               fmaxf(d * acc.y + bb.y, 0.f),
                               fmaxf(d * acc.z + bb.z, 0.f),
                               fmaxf(d * acc.w + bb.w, 0.f));
        *(float4*)(g_h + (size_t)n * F2 + c4 * 4) = o;
    }
}

// ---------------- GEMM2: 128x40 block, 8x4 micro-tile, 160 thr --------------
__global__ void k_gemm2(const float* __restrict__ W) {
    __shared__ float Xs[16][128];  // [k][row]
    __shared__ float Ws[16][40];   // [k][col]
    int tid = threadIdx.x;
    int rbase = blockIdx.x * 128;
    int m0 = (tid / 10) * 8;
    int n0 = (tid % 10) * 4;

    float c[8][4] = {};

    #pragma unroll 1
    for (int kc = 0; kc < F2; kc += 16) {
        for (int idx = tid; idx < 512; idx += 160) {
            int row = idx >> 2, q = idx & 3;
            int rr = min(rbase + row, NN - 1);
            float4 v = *(const float4*)(g_h + (size_t)rr * F2 + kc + q * 4);
            Xs[q * 4 + 0][row] = v.x;
            Xs[q * 4 + 1][row] = v.y;
            Xs[q * 4 + 2][row] = v.z;
            Xs[q * 4 + 3][row] = v.w;
        }
        {
            int k = tid / 10, c4 = tid % 10;
            float4 v = *(const float4*)(W + (size_t)(kc + k) * F3 + c4 * 4);
            *(float4*)&Ws[k][c4 * 4] = v;
        }
        __syncthreads();
        #pragma unroll
        for (int k = 0; k < 16; k++) {
            float4 a0 = *(float4*)&Xs[k][m0];
            float4 a1 = *(float4*)&Xs[k][m0 + 4];
            float4 b  = *(float4*)&Ws[k][n0];
            float av[8] = {a0.x, a0.y, a0.z, a0.w, a1.x, a1.y, a1.z, a1.w};
            #pragma unroll
            for (int i = 0; i < 8; i++) {
                c[i][0] = fmaf(av[i], b.x, c[i][0]);
                c[i][1] = fmaf(av[i], b.y, c[i][1]);
                c[i][2] = fmaf(av[i], b.z, c[i][2]);
                c[i][3] = fmaf(av[i], b.w, c[i][3]);
            }
        }
        __syncthreads();
    }

    #pragma unroll
    for (int i = 0; i < 8; i++) {
        int r = rbase + m0 + i;
        if (r < NN) {
            float d = g_dis[r];
            float4 o = make_float4(c[i][0] * d, c[i][1] * d, c[i][2] * d, c[i][3] * d);
            *(float4*)(g_hwf + (size_t)r * F3 + n0) = o;
        }
    }
}

// ---------------- agg2: float2 gather, 4 edges in flight + log-softmax ------
__global__ void k_agg2(const float* __restrict__ b2, float* __restrict__ out) {
    int lane = threadIdx.x & 31;
    int n = blockIdx.x * 8 + (threadIdx.x >> 5);
    if (n >= NN) return;
    bool act = lane < 20;
    const float2* hw2 = (const float2*)g_hwf;  // 20 per row
    int beg = g_off[n], end = g_off[n + 1];

    float2 aA = make_float2(0.f, 0.f), aB = make_float2(0.f, 0.f);
    float2 aC = make_float2(0.f, 0.f), aD = make_float2(0.f, 0.f);
    if (act) aA = hw2[(size_t)n * 20 + lane];  // self-loop

    for (int base = beg; base < end; base += 32) {
        int cnt = min(32, end - base);
        int sl = (lane < cnt) ? g_csr[base + lane] : 0;
        int k = 0;
        for (; k + 3 < cnt; k += 4) {
            int s0 = __shfl_sync(0xffffffffu, sl, k);
            int s1 = __shfl_sync(0xffffffffu, sl, k + 1);
            int s2 = __shfl_sync(0xffffffffu, sl, k + 2);
            int s3 = __shfl_sync(0xffffffffu, sl, k + 3);
            if (act) {
                float2 v0 = hw2[(size_t)s0 * 20 + lane];
                float2 v1 = hw2[(size_t)s1 * 20 + lane];
                float2 v2 = hw2[(size_t)s2 * 20 + lane];
                float2 v3 = hw2[(size_t)s3 * 20 + lane];
                aA.x += v0.x; aA.y += v0.y;
                aB.x += v1.x; aB.y += v1.y;
                aC.x += v2.x; aC.y += v2.y;
                aD.x += v3.x; aD.y += v3.y;
            }
        }
        for (; k < cnt; k++) {
            int s0 = __shfl_sync(0xffffffffu, sl, k);
            if (act) {
                float2 v = hw2[(size_t)s0 * 20 + lane];
                aA.x += v.x; aA.y += v.y;
            }
        }
    }

    float d = g_dis[n];
    float sx = aA.x + aB.x + aC.x + aD.x;
    float sy = aA.y + aB.y + aC.y + aD.y;
    float zx = act ? d * sx + b2[2 * lane]     : -3.4e38f;
    float zy = act ? d * sy + b2[2 * lane + 1] : -3.4e38f;

    float m = fmaxf(zx, zy);
    #pragma unroll
    for (int o = 16; o; o >>= 1) m = fmaxf(m, __shfl_xor_sync(0xffffffffu, m, o));
    float s = act ? (expf(zx - m) + expf(zy - m)) : 0.f;
    #pragma unroll
    for (int o = 16; o; o >>= 1) s += __shfl_xor_sync(0xffffffffu, s, o);
    float lse = m + logf(s);

    if (act) {
        out[(size_t)n * F3 + 2 * lane]     = zx - lse;
        out[(size_t)n * F3 + 2 * lane + 1] = zy - lse;
    }
}

// ---------------- launcher --------------------------------------------------
extern "C" void kernel_launch(void* const* d_in, const int* in_sizes, int n_in,
                              void* d_out, int out_size) {
    const float* x  = (const float*)d_in[0];
    const void*  ei = d_in[1];
    const float* W1 = (const float*)d_in[2];
    const float* b1 = (const float*)d_in[3];
    const float* W2 = (const float*)d_in[4];
    const float* b2 = (const float*)d_in[5];
    float* out = (float*)d_out;

    int E = in_sizes[1] / 2;
    int eb = (E + 255) / 256;

    static cudaStream_t s2 = 0;
    static cudaEvent_t evA = 0, evB = 0;
    if (!s2) {
        cudaStreamCreateWithFlags(&s2, cudaStreamNonBlocking);
        cudaEventCreateWithFlags(&evA, cudaEventDisableTiming);
        cudaEventCreateWithFlags(&evB, cudaEventDisableTiming);
    }

    k_init<<<NB, 256>>>((const int*)ei);
    k_deg<<<eb, 256>>>(ei, E);
    k_dis_scan1<<<NB, 256>>>();

    // fork: gemm1 (needs only x, W1, dis) overlaps the CSR build
    cudaEventRecord(evA, 0);
    cudaStreamWaitEvent(s2, evA, 0);
    k_gemm1<<<(NN + 127) / 128, 256, 0, s2>>>(x, W1);
    cudaEventRecord(evB, s2);

    k_scan2<<<1, 512>>>();
    k_scan3<<<(NN + 256) / 256, 256>>>();
    k_fill<<<eb, 256>>>(ei, E);

    cudaStreamWaitEvent(0, evB, 0);  // join before agg1

    k_agg1<<<(NN + 7) / 8, 256>>>(b1);
    k_gemm2<<<(NN + 127) / 128, 160>>>(W2);
    k_agg2<<<(NN + 7) / 8, 256>>>(b2, out);
}